// round 9
// baseline (speedup 1.0000x reference)
#include <cuda_runtime.h>
#include <cuda_bf16.h>
#include <math.h>

// ===========================================================================
// Qwen2Attention  B=1 S=4096 HID=2048 NH=16 NKV=4 HD=128, RoPE theta=1e4
// Full fp32 baseline: NT SGEMMs + flash attention (causal, online softmax).
// Scratch in __device__ globals (no allocation). All launches capture-safe.
// ===========================================================================

#define S_LEN 4096
#define HID   2048
#define NH    16
#define NKV   4
#define HD    128
#define KVW   (NKV * HD)   // 512

// ----------------------------- scratch ------------------------------------
__device__ float g_q[S_LEN * HID];      // 32 MB
__device__ float g_k[S_LEN * KVW];      //  8 MB
__device__ float g_v[S_LEN * KVW];      //  8 MB
__device__ float g_attn[S_LEN * HID];   // 32 MB
__device__ float g_cos[S_LEN * (HD/2)];
__device__ float g_sin[S_LEN * (HD/2)];

// ----------------------- RoPE cos/sin table -------------------------------
__global__ void rope_table_kernel() {
    int idx = blockIdx.x * blockDim.x + threadIdx.x;
    if (idx >= S_LEN * (HD/2)) return;
    int d = idx & 63;
    int s = idx >> 6;
    double inv = 1.0 / pow(10000.0, (double)d / 64.0);
    double f = (double)s * inv;
    g_cos[idx] = (float)cos(f);
    g_sin[idx] = (float)sin(f);
}

// ----------------------- RoPE apply (in-place) ----------------------------
// x layout [S][nheads*128]; out[d] = x[d]*c - x[d+64]*s ; out[d+64]=x[d+64]*c + x[d]*s
__global__ void rope_apply_kernel(float* __restrict__ x, int nheads, int total) {
    int idx = blockIdx.x * blockDim.x + threadIdx.x;
    if (idx >= total) return;
    int d = idx & 63;
    int h = (idx >> 6) % nheads;
    int s = idx / (64 * nheads);
    float c  = g_cos[s * 64 + d];
    float sn = g_sin[s * 64 + d];
    float* p = x + (size_t)s * (nheads * HD) + h * HD;
    float x1 = p[d];
    float x2 = p[d + 64];
    p[d]      = x1 * c - x2 * sn;
    p[d + 64] = x2 * c + x1 * sn;
}

// --------------------------- NT SGEMM --------------------------------------
// C[m][n] = sum_k A[m*K+k] * B[n*K+k]  (+ bias[n]).  M,N multiples of 128.
// 128x128 tile, BK=16, 256 threads, 8x8 per thread, register prefetch.
__global__ __launch_bounds__(256, 2) void gemm_nt_kernel(
    const float* __restrict__ A, const float* __restrict__ B,
    const float* __restrict__ bias, float* __restrict__ C,
    int M, int N, int K)
{
    __shared__ float As[16][132];
    __shared__ float Bs[16][132];

    const int bm = blockIdx.y << 7;
    const int bn = blockIdx.x << 7;
    const int t  = threadIdx.x;
    const int tx = t & 15;
    const int ty = t >> 4;
    const int lm = t >> 2;         // 0..63
    const int lk = (t & 3) << 2;   // 0,4,8,12

    const float* Ap = A + (size_t)(bm + lm) * K + lk;
    const float* Bp = B + (size_t)(bn + lm) * K + lk;
    const int ntiles = K >> 4;

    float4 pa0 = *(const float4*)(Ap);
    float4 pa1 = *(const float4*)(Ap + (size_t)64 * K);
    float4 pb0 = *(const float4*)(Bp);
    float4 pb1 = *(const float4*)(Bp + (size_t)64 * K);

    float acc[8][8];
#pragma unroll
    for (int i = 0; i < 8; i++)
#pragma unroll
        for (int j = 0; j < 8; j++) acc[i][j] = 0.f;

    for (int kt = 0; kt < ntiles; kt++) {
        As[lk+0][lm]    = pa0.x; As[lk+1][lm]    = pa0.y; As[lk+2][lm]    = pa0.z; As[lk+3][lm]    = pa0.w;
        As[lk+0][lm+64] = pa1.x; As[lk+1][lm+64] = pa1.y; As[lk+2][lm+64] = pa1.z; As[lk+3][lm+64] = pa1.w;
        Bs[lk+0][lm]    = pb0.x; Bs[lk+1][lm]    = pb0.y; Bs[lk+2][lm]    = pb0.z; Bs[lk+3][lm]    = pb0.w;
        Bs[lk+0][lm+64] = pb1.x; Bs[lk+1][lm+64] = pb1.y; Bs[lk+2][lm+64] = pb1.z; Bs[lk+3][lm+64] = pb1.w;
        __syncthreads();

        if (kt + 1 < ntiles) {
            const float* Ap2 = Ap + (size_t)(kt + 1) * 16;
            const float* Bp2 = Bp + (size_t)(kt + 1) * 16;
            pa0 = *(const float4*)(Ap2);
            pa1 = *(const float4*)(Ap2 + (size_t)64 * K);
            pb0 = *(const float4*)(Bp2);
            pb1 = *(const float4*)(Bp2 + (size_t)64 * K);
        }

#pragma unroll
        for (int k = 0; k < 16; k++) {
            float4 a0 = *(const float4*)&As[k][ty * 4];
            float4 a1 = *(const float4*)&As[k][64 + ty * 4];
            float4 b0 = *(const float4*)&Bs[k][tx * 4];
            float4 b1 = *(const float4*)&Bs[k][64 + tx * 4];
            float av[8] = {a0.x,a0.y,a0.z,a0.w,a1.x,a1.y,a1.z,a1.w};
            float bv[8] = {b0.x,b0.y,b0.z,b0.w,b1.x,b1.y,b1.z,b1.w};
#pragma unroll
            for (int ia = 0; ia < 8; ia++)
#pragma unroll
                for (int jb = 0; jb < 8; jb++)
                    acc[ia][jb] += av[ia] * bv[jb];
        }
        __syncthreads();
    }

    float4 bb0 = make_float4(0.f,0.f,0.f,0.f);
    float4 bb1 = make_float4(0.f,0.f,0.f,0.f);
    if (bias) {
        bb0 = *(const float4*)(bias + bn + tx * 4);
        bb1 = *(const float4*)(bias + bn + 64 + tx * 4);
    }
#pragma unroll
    for (int ia = 0; ia < 8; ia++) {
        int r = bm + ((ia < 4) ? (ty * 4 + ia) : (64 + ty * 4 + ia - 4));
        float4 v0 = make_float4(acc[ia][0]+bb0.x, acc[ia][1]+bb0.y, acc[ia][2]+bb0.z, acc[ia][3]+bb0.w);
        float4 v1 = make_float4(acc[ia][4]+bb1.x, acc[ia][5]+bb1.y, acc[ia][6]+bb1.z, acc[ia][7]+bb1.w);
        *(float4*)(C + (size_t)r * N + bn + tx * 4)      = v0;
        *(float4*)(C + (size_t)r * N + bn + 64 + tx * 4) = v1;
    }
}

// ------------------------- flash attention ---------------------------------
// grid (64, 16): x -> query tile (reversed for load balance), y -> head.
// BM=BN=64, D=128, 256 threads. Dynamic smem 112 KB:
//   Qs[128][64] (transposed, pre-scaled), Ks[128][64], Vs[64][128], Ps[64][64]
#define FLASH_SMEM ((128*64 + 128*64 + 64*128 + 64*64) * 4)

__global__ __launch_bounds__(256, 2) void flash_kernel(
    const float* __restrict__ Q, const float* __restrict__ K,
    const float* __restrict__ V, float* __restrict__ O)
{
    extern __shared__ float sm[];
    float* Qs = sm;           // [128][64]
    float* Ks = sm + 8192;    // [128][64]
    float* Vs = sm + 16384;   // [64][128]
    float* Ps = sm + 24576;   // [64][64]

    const int h   = blockIdx.y;
    const int qb  = 63 - (int)blockIdx.x;       // big tiles first
    const int kvh = h >> 2;                      // GQA: group of 4
    const int t   = threadIdx.x;
    const int tx  = t & 15;
    const int ty  = t >> 4;
    const float scale = 0.08838834764831845f;    // 1/sqrt(128)

    // Load Q tile transposed & pre-scaled: Qs[k][m]
    const float* Qg = Q + (size_t)(qb * 64) * HID + h * HD;
    for (int idx = t; idx < 2048; idx += 256) {
        int n = idx & 63, kv = idx >> 6;
        float4 v4 = *(const float4*)(Qg + (size_t)n * HID + (kv << 2));
        int b = (kv << 2) * 64 + n;
        Qs[b] = v4.x * scale; Qs[b+64] = v4.y * scale;
        Qs[b+128] = v4.z * scale; Qs[b+192] = v4.w * scale;
    }

    float o[32];
    float m_r[4], l_r[4];
#pragma unroll
    for (int i = 0; i < 32; i++) o[i] = 0.f;
#pragma unroll
    for (int i = 0; i < 4; i++) { m_r[i] = -1e30f; l_r[i] = 0.f; }

    for (int kb = 0; kb <= qb; kb++) {
        __syncthreads();   // previous iter done with Ks/Vs/Ps (also covers Qs load)

        const float* Kg = K + (size_t)(kb * 64) * KVW + kvh * HD;
        const float* Vg = V + (size_t)(kb * 64) * KVW + kvh * HD;
        for (int idx = t; idx < 2048; idx += 256) {     // K transposed: Ks[k][n]
            int n = idx & 63, kv = idx >> 6;
            float4 v4 = *(const float4*)(Kg + (size_t)n * KVW + (kv << 2));
            int b = (kv << 2) * 64 + n;
            Ks[b] = v4.x; Ks[b+64] = v4.y; Ks[b+128] = v4.z; Ks[b+192] = v4.w;
        }
        for (int idx = t; idx < 2048; idx += 256) {     // V natural: Vs[j][d]
            int j = idx >> 5, dv = idx & 31;
            *(float4*)(Vs + j * 128 + (dv << 2)) =
                *(const float4*)(Vg + (size_t)j * KVW + (dv << 2));
        }
        __syncthreads();

        // S = Q K^T (already scaled): thread owns rows ty*4+i, cols tx*4+j
        float s[16];
#pragma unroll
        for (int i = 0; i < 16; i++) s[i] = 0.f;
#pragma unroll 8
        for (int k = 0; k < 128; k++) {
            float4 a = *(const float4*)&Qs[k * 64 + ty * 4];
            float4 b = *(const float4*)&Ks[k * 64 + tx * 4];
            s[0]  += a.x*b.x; s[1]  += a.x*b.y; s[2]  += a.x*b.z; s[3]  += a.x*b.w;
            s[4]  += a.y*b.x; s[5]  += a.y*b.y; s[6]  += a.y*b.z; s[7]  += a.y*b.w;
            s[8]  += a.z*b.x; s[9]  += a.z*b.y; s[10] += a.z*b.z; s[11] += a.z*b.w;
            s[12] += a.w*b.x; s[13] += a.w*b.y; s[14] += a.w*b.z; s[15] += a.w*b.w;
        }

        if (kb == qb) {   // diagonal tile: causal mask
#pragma unroll
            for (int i = 0; i < 4; i++)
#pragma unroll
                for (int j = 0; j < 4; j++)
                    if (tx * 4 + j > ty * 4 + i) s[i*4+j] = -1e30f;
        }

        // online softmax; rows spread over 16 consecutive lanes (half-warp)
#pragma unroll
        for (int i = 0; i < 4; i++) {
            float mx = fmaxf(fmaxf(s[i*4], s[i*4+1]), fmaxf(s[i*4+2], s[i*4+3]));
#pragma unroll
            for (int off = 8; off >= 1; off >>= 1)
                mx = fmaxf(mx, __shfl_xor_sync(0xffffffffu, mx, off, 16));
            float mnew = fmaxf(m_r[i], mx);
            float corr = __expf(m_r[i] - mnew);
            m_r[i] = mnew;
            float p0 = __expf(s[i*4+0] - mnew);
            float p1 = __expf(s[i*4+1] - mnew);
            float p2 = __expf(s[i*4+2] - mnew);
            float p3 = __expf(s[i*4+3] - mnew);
            float ls = p0 + p1 + p2 + p3;
#pragma unroll
            for (int off = 8; off >= 1; off >>= 1)
                ls += __shfl_xor_sync(0xffffffffu, ls, off, 16);
            l_r[i] = l_r[i] * corr + ls;
#pragma unroll
            for (int c = 0; c < 8; c++) o[i*8+c] *= corr;
            *(float4*)&Ps[(ty * 4 + i) * 64 + tx * 4] = make_float4(p0, p1, p2, p3);
        }
        __syncthreads();   // Ps ready

        // O += P @ V : thread owns rows ty*4+i, cols {tx*4.., 64+tx*4..}
#pragma unroll 2
        for (int j = 0; j < 64; j += 4) {
            float4 pa[4];
#pragma unroll
            for (int i = 0; i < 4; i++)
                pa[i] = *(const float4*)&Ps[(ty * 4 + i) * 64 + j];
#pragma unroll
            for (int jj = 0; jj < 4; jj++) {
                float4 b0 = *(const float4*)&Vs[(j + jj) * 128 + tx * 4];
                float4 b1 = *(const float4*)&Vs[(j + jj) * 128 + 64 + tx * 4];
#pragma unroll
                for (int i = 0; i < 4; i++) {
                    float p = (jj == 0) ? pa[i].x : (jj == 1) ? pa[i].y
                            : (jj == 2) ? pa[i].z : pa[i].w;
                    o[i*8+0] += p * b0.x; o[i*8+1] += p * b0.y;
                    o[i*8+2] += p * b0.z; o[i*8+3] += p * b0.w;
                    o[i*8+4] += p * b1.x; o[i*8+5] += p * b1.y;
                    o[i*8+6] += p * b1.z; o[i*8+7] += p * b1.w;
                }
            }
        }
    }

    // epilogue: divide by l, write [s][h*128 + d]
    float* Og = O + (size_t)(qb * 64) * HID + h * HD;
#pragma unroll
    for (int i = 0; i < 4; i++) {
        float inv = 1.f / l_r[i];
        float* row = Og + (size_t)(ty * 4 + i) * HID;
        *(float4*)(row + tx * 4) =
            make_float4(o[i*8+0]*inv, o[i*8+1]*inv, o[i*8+2]*inv, o[i*8+3]*inv);
        *(float4*)(row + 64 + tx * 4) =
            make_float4(o[i*8+4]*inv, o[i*8+5]*inv, o[i*8+6]*inv, o[i*8+7]*inv);
    }
}

// --------------------------------------------------------------------------
extern "C" void kernel_launch(void* const* d_in, const int* in_sizes, int n_in,
                              void* d_out, int out_size)
{
    const float* hs  = (const float*)d_in[0];
    // d_in[1] = attention_mask (pure causal; implemented directly, not read)
    const float* q_w = (const float*)d_in[2];
    const float* q_b = (const float*)d_in[3];
    const float* k_w = (const float*)d_in[4];
    const float* k_b = (const float*)d_in[5];
    const float* v_w = (const float*)d_in[6];
    const float* v_b = (const float*)d_in[7];
    const float* o_w = (const float*)d_in[8];
    float* out = (float*)d_out;
    (void)in_sizes; (void)n_in; (void)out_size;

    void *pq, *pk, *pv, *pa;
    cudaGetSymbolAddress(&pq, g_q);
    cudaGetSymbolAddress(&pk, g_k);
    cudaGetSymbolAddress(&pv, g_v);
    cudaGetSymbolAddress(&pa, g_attn);
    float* qf = (float*)pq;
    float* kf = (float*)pk;
    float* vf = (float*)pv;
    float* af = (float*)pa;

    cudaFuncSetAttribute(flash_kernel,
                         cudaFuncAttributeMaxDynamicSharedMemorySize, FLASH_SMEM);

    // 1. RoPE table
    rope_table_kernel<<<(S_LEN * 64 + 255) / 256, 256>>>();

    // 2. projections (NT: y = x @ W^T + b)
    gemm_nt_kernel<<<dim3(HID / 128, S_LEN / 128), 256>>>(hs, q_w, q_b, qf, S_LEN, HID, HID);
    gemm_nt_kernel<<<dim3(KVW / 128, S_LEN / 128), 256>>>(hs, k_w, k_b, kf, S_LEN, KVW, HID);
    gemm_nt_kernel<<<dim3(KVW / 128, S_LEN / 128), 256>>>(hs, v_w, v_b, vf, S_LEN, KVW, HID);

    // 3. RoPE on q and k
    rope_apply_kernel<<<(S_LEN * NH * 64 + 255) / 256, 256>>>(qf, NH, S_LEN * NH * 64);
    rope_apply_kernel<<<(S_LEN * NKV * 64 + 255) / 256, 256>>>(kf, NKV, S_LEN * NKV * 64);

    // 4. causal flash attention (GQA)
    flash_kernel<<<dim3(64, NH), 256, FLASH_SMEM>>>(qf, kf, vf, af);

    // 5. output projection
    gemm_nt_kernel<<<dim3(HID / 128, S_LEN / 128), 256>>>(af, o_w, (const float*)nullptr,
                                                          out, S_LEN, HID, HID);
}

// round 10
// speedup vs baseline: 1.3703x; 1.3703x over previous
#include <cuda_runtime.h>
#include <cuda_bf16.h>
#include <math.h>

// ===========================================================================
// Qwen2Attention  B=1 S=4096 HID=2048 NH=16 NKV=4 HD=128, RoPE theta=1e4
// R10: projection GEMMs on tensor pipe (mma.sync tf32, fp32 accumulate).
// Flash attention still fp32 FFMA (next target). Scratch in __device__ globals.
// ===========================================================================

#define S_LEN 4096
#define HID   2048
#define NH    16
#define NKV   4
#define HD    128
#define KVW   (NKV * HD)   // 512

// ----------------------------- scratch ------------------------------------
__device__ float g_q[S_LEN * HID];      // 32 MB
__device__ float g_k[S_LEN * KVW];      //  8 MB
__device__ float g_v[S_LEN * KVW];      //  8 MB
__device__ float g_attn[S_LEN * HID];   // 32 MB
__device__ float g_cos[S_LEN * (HD/2)];
__device__ float g_sin[S_LEN * (HD/2)];

// ----------------------- RoPE cos/sin table -------------------------------
__global__ void rope_table_kernel() {
    int idx = blockIdx.x * blockDim.x + threadIdx.x;
    if (idx >= S_LEN * (HD/2)) return;
    int d = idx & 63;
    int s = idx >> 6;
    double inv = 1.0 / pow(10000.0, (double)d / 64.0);
    double f = (double)s * inv;
    g_cos[idx] = (float)cos(f);
    g_sin[idx] = (float)sin(f);
}

// ----------------------- RoPE apply (in-place) ----------------------------
__global__ void rope_apply_kernel(float* __restrict__ x, int nheads, int total) {
    int idx = blockIdx.x * blockDim.x + threadIdx.x;
    if (idx >= total) return;
    int d = idx & 63;
    int h = (idx >> 6) % nheads;
    int s = idx / (64 * nheads);
    float c  = g_cos[s * 64 + d];
    float sn = g_sin[s * 64 + d];
    float* p = x + (size_t)s * (nheads * HD) + h * HD;
    float x1 = p[d];
    float x2 = p[d + 64];
    p[d]      = x1 * c - x2 * sn;
    p[d + 64] = x2 * c + x1 * sn;
}

// ------------------------- tf32 helpers ------------------------------------
__device__ __forceinline__ unsigned f2tf32(float x) {
    unsigned r;
    asm("cvt.rna.tf32.f32 %0, %1;" : "=r"(r) : "f"(x));
    return r;
}

__device__ __forceinline__ void mma_tf32(
    float& c0, float& c1, float& c2, float& c3,
    unsigned a0, unsigned a1, unsigned a2, unsigned a3,
    unsigned b0, unsigned b1)
{
    asm volatile(
        "mma.sync.aligned.m16n8k8.row.col.f32.tf32.tf32.f32 "
        "{%0,%1,%2,%3}, {%4,%5,%6,%7}, {%8,%9}, {%0,%1,%2,%3};\n"
        : "+f"(c0), "+f"(c1), "+f"(c2), "+f"(c3)
        : "r"(a0), "r"(a1), "r"(a2), "r"(a3), "r"(b0), "r"(b1));
}

// --------------------------- NT GEMM (tf32 tensor) --------------------------
// C[m][n] = sum_k A[m*K+k] * B[n*K+k]  (+ bias[n]).  M,N mult of 128, K mult 64.
// BM=128, BN=128, BK=64. 256 threads = 8 warps as 4(m) x 2(n); warp = 32x64.
// SMEM rows stride 68 floats: frag reads (4m+k)%32 conflict-free; STS.128
// writes contiguous per quarter-warp. Inputs cvt.rna.tf32 in producer.
#define GEMM_SMEM (2 * 128 * 68 * 4)   // 69632 B

__global__ __launch_bounds__(256, 2) void gemm_tf32_kernel(
    const float* __restrict__ A, const float* __restrict__ B,
    const float* __restrict__ bias, float* __restrict__ C,
    int M, int N, int K)
{
    extern __shared__ unsigned smem_u[];
    unsigned* As = smem_u;              // [128][68]
    unsigned* Bs = smem_u + 128 * 68;   // [128][68]

    const int bm = blockIdx.y << 7;
    const int bn = blockIdx.x << 7;
    const int t  = threadIdx.x;
    const int lane = t & 31;
    const int warp = t >> 5;
    const int wm = warp >> 1;           // 0..3 -> m offset wm*32
    const int wn = warp & 1;            // 0..1 -> n offset wn*64
    const int g  = lane >> 2;           // groupID 0..7
    const int tq = lane & 3;            // threadID_in_group 0..3

    // producer mapping: thread loads float4 at (row = tm + 16*i, k = tk)
    const int tm = t >> 4;              // 0..15
    const int tk = (t & 15) << 2;       // 0..60

    float acc[2][8][4];
#pragma unroll
    for (int mi = 0; mi < 2; mi++)
#pragma unroll
        for (int j = 0; j < 8; j++)
#pragma unroll
            for (int r = 0; r < 4; r++) acc[mi][j][r] = 0.f;

    const int ntiles = K >> 6;
    for (int kt = 0; kt < ntiles; kt++) {
        // ---- produce: global -> cvt tf32 -> smem ----
        const float* Ag = A + (size_t)bm * K + (size_t)kt * 64 + tk;
        const float* Bg = B + (size_t)bn * K + (size_t)kt * 64 + tk;
#pragma unroll
        for (int i = 0; i < 8; i++) {
            int m = tm + 16 * i;
            float4 va = *(const float4*)(Ag + (size_t)m * K);
            float4 vb = *(const float4*)(Bg + (size_t)m * K);
            uint4 ua = make_uint4(f2tf32(va.x), f2tf32(va.y), f2tf32(va.z), f2tf32(va.w));
            uint4 ub = make_uint4(f2tf32(vb.x), f2tf32(vb.y), f2tf32(vb.z), f2tf32(vb.w));
            *(uint4*)(As + m * 68 + tk) = ua;
            *(uint4*)(Bs + m * 68 + tk) = ub;
        }
        __syncthreads();

        // ---- consume: 8 k-steps of m16n8k8 ----
#pragma unroll
        for (int ks = 0; ks < 8; ks++) {
            const int k0 = ks * 8;
            unsigned a[2][4];
#pragma unroll
            for (int mi = 0; mi < 2; mi++) {
                const unsigned* ap = As + (wm * 32 + mi * 16 + g) * 68 + k0 + tq;
                a[mi][0] = ap[0];
                a[mi][2] = ap[4];
                a[mi][1] = ap[8 * 68];
                a[mi][3] = ap[8 * 68 + 4];
            }
#pragma unroll
            for (int half = 0; half < 2; half++) {
                unsigned b[4][2];
#pragma unroll
                for (int jj = 0; jj < 4; jj++) {
                    const unsigned* bp = Bs + (wn * 64 + (half * 4 + jj) * 8 + g) * 68 + k0 + tq;
                    b[jj][0] = bp[0];
                    b[jj][1] = bp[4];
                }
#pragma unroll
                for (int mi = 0; mi < 2; mi++)
#pragma unroll
                    for (int jj = 0; jj < 4; jj++) {
                        int j = half * 4 + jj;
                        mma_tf32(acc[mi][j][0], acc[mi][j][1], acc[mi][j][2], acc[mi][j][3],
                                 a[mi][0], a[mi][1], a[mi][2], a[mi][3],
                                 b[jj][0], b[jj][1]);
                    }
            }
        }
        __syncthreads();
    }

    // ---- epilogue: bias + store ----
#pragma unroll
    for (int mi = 0; mi < 2; mi++) {
        int row = bm + wm * 32 + mi * 16 + g;
#pragma unroll
        for (int j = 0; j < 8; j++) {
            int col = bn + wn * 64 + j * 8 + 2 * tq;
            float b0 = 0.f, b1 = 0.f;
            if (bias) { b0 = bias[col]; b1 = bias[col + 1]; }
            *(float2*)(C + (size_t)row * N + col) =
                make_float2(acc[mi][j][0] + b0, acc[mi][j][1] + b1);
            *(float2*)(C + (size_t)(row + 8) * N + col) =
                make_float2(acc[mi][j][2] + b0, acc[mi][j][3] + b1);
        }
    }
}

// ------------------------- flash attention ---------------------------------
// grid (64, 16): x -> query tile (reversed for load balance), y -> head.
// BM=BN=64, D=128, 256 threads. Dynamic smem 112 KB.
#define FLASH_SMEM ((128*64 + 128*64 + 64*128 + 64*64) * 4)

__global__ __launch_bounds__(256, 2) void flash_kernel(
    const float* __restrict__ Q, const float* __restrict__ K,
    const float* __restrict__ V, float* __restrict__ O)
{
    extern __shared__ float sm[];
    float* Qs = sm;           // [128][64]
    float* Ks = sm + 8192;    // [128][64]
    float* Vs = sm + 16384;   // [64][128]
    float* Ps = sm + 24576;   // [64][64]

    const int h   = blockIdx.y;
    const int qb  = 63 - (int)blockIdx.x;       // big tiles first
    const int kvh = h >> 2;                      // GQA: group of 4
    const int t   = threadIdx.x;
    const int tx  = t & 15;
    const int ty  = t >> 4;
    const float scale = 0.08838834764831845f;    // 1/sqrt(128)

    const float* Qg = Q + (size_t)(qb * 64) * HID + h * HD;
    for (int idx = t; idx < 2048; idx += 256) {
        int n = idx & 63, kv = idx >> 6;
        float4 v4 = *(const float4*)(Qg + (size_t)n * HID + (kv << 2));
        int b = (kv << 2) * 64 + n;
        Qs[b] = v4.x * scale; Qs[b+64] = v4.y * scale;
        Qs[b+128] = v4.z * scale; Qs[b+192] = v4.w * scale;
    }

    float o[32];
    float m_r[4], l_r[4];
#pragma unroll
    for (int i = 0; i < 32; i++) o[i] = 0.f;
#pragma unroll
    for (int i = 0; i < 4; i++) { m_r[i] = -1e30f; l_r[i] = 0.f; }

    for (int kb = 0; kb <= qb; kb++) {
        __syncthreads();

        const float* Kg = K + (size_t)(kb * 64) * KVW + kvh * HD;
        const float* Vg = V + (size_t)(kb * 64) * KVW + kvh * HD;
        for (int idx = t; idx < 2048; idx += 256) {     // K transposed: Ks[k][n]
            int n = idx & 63, kv = idx >> 6;
            float4 v4 = *(const float4*)(Kg + (size_t)n * KVW + (kv << 2));
            int b = (kv << 2) * 64 + n;
            Ks[b] = v4.x; Ks[b+64] = v4.y; Ks[b+128] = v4.z; Ks[b+192] = v4.w;
        }
        for (int idx = t; idx < 2048; idx += 256) {     // V natural: Vs[j][d]
            int j = idx >> 5, dv = idx & 31;
            *(float4*)(Vs + j * 128 + (dv << 2)) =
                *(const float4*)(Vg + (size_t)j * KVW + (dv << 2));
        }
        __syncthreads();

        float s[16];
#pragma unroll
        for (int i = 0; i < 16; i++) s[i] = 0.f;
#pragma unroll 8
        for (int k = 0; k < 128; k++) {
            float4 a = *(const float4*)&Qs[k * 64 + ty * 4];
            float4 b = *(const float4*)&Ks[k * 64 + tx * 4];
            s[0]  += a.x*b.x; s[1]  += a.x*b.y; s[2]  += a.x*b.z; s[3]  += a.x*b.w;
            s[4]  += a.y*b.x; s[5]  += a.y*b.y; s[6]  += a.y*b.z; s[7]  += a.y*b.w;
            s[8]  += a.z*b.x; s[9]  += a.z*b.y; s[10] += a.z*b.z; s[11] += a.z*b.w;
            s[12] += a.w*b.x; s[13] += a.w*b.y; s[14] += a.w*b.z; s[15] += a.w*b.w;
        }

        if (kb == qb) {
#pragma unroll
            for (int i = 0; i < 4; i++)
#pragma unroll
                for (int j = 0; j < 4; j++)
                    if (tx * 4 + j > ty * 4 + i) s[i*4+j] = -1e30f;
        }

#pragma unroll
        for (int i = 0; i < 4; i++) {
            float mx = fmaxf(fmaxf(s[i*4], s[i*4+1]), fmaxf(s[i*4+2], s[i*4+3]));
#pragma unroll
            for (int off = 8; off >= 1; off >>= 1)
                mx = fmaxf(mx, __shfl_xor_sync(0xffffffffu, mx, off, 16));
            float mnew = fmaxf(m_r[i], mx);
            float corr = __expf(m_r[i] - mnew);
            m_r[i] = mnew;
            float p0 = __expf(s[i*4+0] - mnew);
            float p1 = __expf(s[i*4+1] - mnew);
            float p2 = __expf(s[i*4+2] - mnew);
            float p3 = __expf(s[i*4+3] - mnew);
            float ls = p0 + p1 + p2 + p3;
#pragma unroll
            for (int off = 8; off >= 1; off >>= 1)
                ls += __shfl_xor_sync(0xffffffffu, ls, off, 16);
            l_r[i] = l_r[i] * corr + ls;
#pragma unroll
            for (int c = 0; c < 8; c++) o[i*8+c] *= corr;
            *(float4*)&Ps[(ty * 4 + i) * 64 + tx * 4] = make_float4(p0, p1, p2, p3);
        }
        __syncthreads();

#pragma unroll 2
        for (int j = 0; j < 64; j += 4) {
            float4 pa[4];
#pragma unroll
            for (int i = 0; i < 4; i++)
                pa[i] = *(const float4*)&Ps[(ty * 4 + i) * 64 + j];
#pragma unroll
            for (int jj = 0; jj < 4; jj++) {
                float4 b0 = *(const float4*)&Vs[(j + jj) * 128 + tx * 4];
                float4 b1 = *(const float4*)&Vs[(j + jj) * 128 + 64 + tx * 4];
#pragma unroll
                for (int i = 0; i < 4; i++) {
                    float p = (jj == 0) ? pa[i].x : (jj == 1) ? pa[i].y
                            : (jj == 2) ? pa[i].z : pa[i].w;
                    o[i*8+0] += p * b0.x; o[i*8+1] += p * b0.y;
                    o[i*8+2] += p * b0.z; o[i*8+3] += p * b0.w;
                    o[i*8+4] += p * b1.x; o[i*8+5] += p * b1.y;
                    o[i*8+6] += p * b1.z; o[i*8+7] += p * b1.w;
                }
            }
        }
    }

    float* Og = O + (size_t)(qb * 64) * HID + h * HD;
#pragma unroll
    for (int i = 0; i < 4; i++) {
        float inv = 1.f / l_r[i];
        float* row = Og + (size_t)(ty * 4 + i) * HID;
        *(float4*)(row + tx * 4) =
            make_float4(o[i*8+0]*inv, o[i*8+1]*inv, o[i*8+2]*inv, o[i*8+3]*inv);
        *(float4*)(row + 64 + tx * 4) =
            make_float4(o[i*8+4]*inv, o[i*8+5]*inv, o[i*8+6]*inv, o[i*8+7]*inv);
    }
}

// --------------------------------------------------------------------------
extern "C" void kernel_launch(void* const* d_in, const int* in_sizes, int n_in,
                              void* d_out, int out_size)
{
    const float* hs  = (const float*)d_in[0];
    // d_in[1] = attention_mask (pure causal; implemented directly, not read)
    const float* q_w = (const float*)d_in[2];
    const float* q_b = (const float*)d_in[3];
    const float* k_w = (const float*)d_in[4];
    const float* k_b = (const float*)d_in[5];
    const float* v_w = (const float*)d_in[6];
    const float* v_b = (const float*)d_in[7];
    const float* o_w = (const float*)d_in[8];
    float* out = (float*)d_out;
    (void)in_sizes; (void)n_in; (void)out_size;

    void *pq, *pk, *pv, *pa;
    cudaGetSymbolAddress(&pq, g_q);
    cudaGetSymbolAddress(&pk, g_k);
    cudaGetSymbolAddress(&pv, g_v);
    cudaGetSymbolAddress(&pa, g_attn);
    float* qf = (float*)pq;
    float* kf = (float*)pk;
    float* vf = (float*)pv;
    float* af = (float*)pa;

    cudaFuncSetAttribute(flash_kernel,
                         cudaFuncAttributeMaxDynamicSharedMemorySize, FLASH_SMEM);
    cudaFuncSetAttribute(gemm_tf32_kernel,
                         cudaFuncAttributeMaxDynamicSharedMemorySize, GEMM_SMEM);

    // 1. RoPE table
    rope_table_kernel<<<(S_LEN * 64 + 255) / 256, 256>>>();

    // 2. projections (NT: y = x @ W^T + b) on tensor pipe
    gemm_tf32_kernel<<<dim3(HID / 128, S_LEN / 128), 256, GEMM_SMEM>>>(
        hs, q_w, q_b, qf, S_LEN, HID, HID);
    gemm_tf32_kernel<<<dim3(KVW / 128, S_LEN / 128), 256, GEMM_SMEM>>>(
        hs, k_w, k_b, kf, S_LEN, KVW, HID);
    gemm_tf32_kernel<<<dim3(KVW / 128, S_LEN / 128), 256, GEMM_SMEM>>>(
        hs, v_w, v_b, vf, S_LEN, KVW, HID);

    // 3. RoPE on q and k
    rope_apply_kernel<<<(S_LEN * NH * 64 + 255) / 256, 256>>>(qf, NH, S_LEN * NH * 64);
    rope_apply_kernel<<<(S_LEN * NKV * 64 + 255) / 256, 256>>>(kf, NKV, S_LEN * NKV * 64);

    // 4. causal flash attention (GQA)
    flash_kernel<<<dim3(64, NH), 256, FLASH_SMEM>>>(qf, kf, vf, af);

    // 5. output projection
    gemm_tf32_kernel<<<dim3(HID / 128, S_LEN / 128), 256, GEMM_SMEM>>>(
        af, o_w, (const float*)nullptr, out, S_LEN, HID, HID);
}

// round 12
// speedup vs baseline: 2.6331x; 1.9216x over previous
#include <cuda_runtime.h>
#include <cuda_bf16.h>
#include <math.h>

// ===========================================================================
// Qwen2Attention  B=1 S=4096 HID=2048 NH=16 NKV=4 HD=128, RoPE theta=1e4
// R11: flash attention moved to tensor pipe (mma.sync tf32), warp-local
// softmax (BM=128 strip per 8 warps). Projection GEMMs tf32 (unchanged).
// ===========================================================================

#define S_LEN 4096
#define HID   2048
#define NH    16
#define NKV   4
#define HD    128
#define KVW   (NKV * HD)   // 512

// ----------------------------- scratch ------------------------------------
__device__ float g_q[S_LEN * HID];      // 32 MB
__device__ float g_k[S_LEN * KVW];      //  8 MB
__device__ float g_v[S_LEN * KVW];      //  8 MB
__device__ float g_attn[S_LEN * HID];   // 32 MB
__device__ float g_cos[S_LEN * (HD/2)];
__device__ float g_sin[S_LEN * (HD/2)];

// ----------------------- RoPE cos/sin table -------------------------------
__global__ void rope_table_kernel() {
    int idx = blockIdx.x * blockDim.x + threadIdx.x;
    if (idx >= S_LEN * (HD/2)) return;
    int d = idx & 63;
    int s = idx >> 6;
    double inv = 1.0 / pow(10000.0, (double)d / 64.0);
    double f = (double)s * inv;
    g_cos[idx] = (float)cos(f);
    g_sin[idx] = (float)sin(f);
}

// ----------------------- RoPE apply (in-place) ----------------------------
__global__ void rope_apply_kernel(float* __restrict__ x, int nheads, int total) {
    int idx = blockIdx.x * blockDim.x + threadIdx.x;
    if (idx >= total) return;
    int d = idx & 63;
    int h = (idx >> 6) % nheads;
    int s = idx / (64 * nheads);
    float c  = g_cos[s * 64 + d];
    float sn = g_sin[s * 64 + d];
    float* p = x + (size_t)s * (nheads * HD) + h * HD;
    float x1 = p[d];
    float x2 = p[d + 64];
    p[d]      = x1 * c - x2 * sn;
    p[d + 64] = x2 * c + x1 * sn;
}

// ------------------------- tf32 helpers ------------------------------------
__device__ __forceinline__ unsigned f2tf32(float x) {
    unsigned r;
    asm("cvt.rna.tf32.f32 %0, %1;" : "=r"(r) : "f"(x));
    return r;
}

__device__ __forceinline__ void mma_tf32(
    float& c0, float& c1, float& c2, float& c3,
    unsigned a0, unsigned a1, unsigned a2, unsigned a3,
    unsigned b0, unsigned b1)
{
    asm volatile(
        "mma.sync.aligned.m16n8k8.row.col.f32.tf32.tf32.f32 "
        "{%0,%1,%2,%3}, {%4,%5,%6,%7}, {%8,%9}, {%0,%1,%2,%3};\n"
        : "+f"(c0), "+f"(c1), "+f"(c2), "+f"(c3)
        : "r"(a0), "r"(a1), "r"(a2), "r"(a3), "r"(b0), "r"(b1));
}

// --------------------------- NT GEMM (tf32 tensor) --------------------------
#define GEMM_SMEM (2 * 128 * 68 * 4)   // 69632 B

__global__ __launch_bounds__(256, 2) void gemm_tf32_kernel(
    const float* __restrict__ A, const float* __restrict__ B,
    const float* __restrict__ bias, float* __restrict__ C,
    int M, int N, int K)
{
    extern __shared__ unsigned smem_u[];
    unsigned* As = smem_u;              // [128][68]
    unsigned* Bs = smem_u + 128 * 68;   // [128][68]

    const int bm = blockIdx.y << 7;
    const int bn = blockIdx.x << 7;
    const int t  = threadIdx.x;
    const int lane = t & 31;
    const int warp = t >> 5;
    const int wm = warp >> 1;
    const int wn = warp & 1;
    const int g  = lane >> 2;
    const int tq = lane & 3;

    const int tm = t >> 4;
    const int tk = (t & 15) << 2;

    float acc[2][8][4];
#pragma unroll
    for (int mi = 0; mi < 2; mi++)
#pragma unroll
        for (int j = 0; j < 8; j++)
#pragma unroll
            for (int r = 0; r < 4; r++) acc[mi][j][r] = 0.f;

    const int ntiles = K >> 6;
    for (int kt = 0; kt < ntiles; kt++) {
        const float* Ag = A + (size_t)bm * K + (size_t)kt * 64 + tk;
        const float* Bg = B + (size_t)bn * K + (size_t)kt * 64 + tk;
#pragma unroll
        for (int i = 0; i < 8; i++) {
            int m = tm + 16 * i;
            float4 va = *(const float4*)(Ag + (size_t)m * K);
            float4 vb = *(const float4*)(Bg + (size_t)m * K);
            uint4 ua = make_uint4(f2tf32(va.x), f2tf32(va.y), f2tf32(va.z), f2tf32(va.w));
            uint4 ub = make_uint4(f2tf32(vb.x), f2tf32(vb.y), f2tf32(vb.z), f2tf32(vb.w));
            *(uint4*)(As + m * 68 + tk) = ua;
            *(uint4*)(Bs + m * 68 + tk) = ub;
        }
        __syncthreads();

#pragma unroll
        for (int ks = 0; ks < 8; ks++) {
            const int k0 = ks * 8;
            unsigned a[2][4];
#pragma unroll
            for (int mi = 0; mi < 2; mi++) {
                const unsigned* ap = As + (wm * 32 + mi * 16 + g) * 68 + k0 + tq;
                a[mi][0] = ap[0];
                a[mi][2] = ap[4];
                a[mi][1] = ap[8 * 68];
                a[mi][3] = ap[8 * 68 + 4];
            }
#pragma unroll
            for (int half = 0; half < 2; half++) {
                unsigned b[4][2];
#pragma unroll
                for (int jj = 0; jj < 4; jj++) {
                    const unsigned* bp = Bs + (wn * 64 + (half * 4 + jj) * 8 + g) * 68 + k0 + tq;
                    b[jj][0] = bp[0];
                    b[jj][1] = bp[4];
                }
#pragma unroll
                for (int mi = 0; mi < 2; mi++)
#pragma unroll
                    for (int jj = 0; jj < 4; jj++) {
                        int j = half * 4 + jj;
                        mma_tf32(acc[mi][j][0], acc[mi][j][1], acc[mi][j][2], acc[mi][j][3],
                                 a[mi][0], a[mi][1], a[mi][2], a[mi][3],
                                 b[jj][0], b[jj][1]);
                    }
            }
        }
        __syncthreads();
    }

#pragma unroll
    for (int mi = 0; mi < 2; mi++) {
        int row = bm + wm * 32 + mi * 16 + g;
#pragma unroll
        for (int j = 0; j < 8; j++) {
            int col = bn + wn * 64 + j * 8 + 2 * tq;
            float b0 = 0.f, b1 = 0.f;
            if (bias) { b0 = bias[col]; b1 = bias[col + 1]; }
            *(float2*)(C + (size_t)row * N + col) =
                make_float2(acc[mi][j][0] + b0, acc[mi][j][1] + b1);
            *(float2*)(C + (size_t)(row + 8) * N + col) =
                make_float2(acc[mi][j][2] + b0, acc[mi][j][3] + b1);
        }
    }
}

// --------------------- flash attention (tf32 tensor) ------------------------
// grid (32, 16): x -> q tile of 128 rows (reversed), y -> head.
// 256 threads = 8 warps; warp w owns rows [w*16, w*16+16) -> softmax warp-local.
// SMEM (tf32): Qs[128][132], Ks[64][132] (token-major, natural copy),
//              Vs[64][132] (token-major, natural copy), Ps[128][68].
#define FL_SMEM ((128*132 + 64*132 + 64*132 + 128*68) * 4)   // 169984 B

__global__ __launch_bounds__(256, 1) void flash_tf32_kernel(
    const float* __restrict__ Q, const float* __restrict__ K,
    const float* __restrict__ V, float* __restrict__ O)
{
    extern __shared__ unsigned fsm[];
    unsigned* Qs = fsm;                       // [128][132]
    unsigned* Ks = Qs + 128 * 132;            // [64][132]
    unsigned* Vs = Ks + 64 * 132;             // [64][132]
    unsigned* Ps = Vs + 64 * 132;             // [128][68]

    const int h   = blockIdx.y;
    const int qb  = 31 - (int)blockIdx.x;     // big tiles first
    const int kvh = h >> 2;                   // GQA group of 4
    const int t    = threadIdx.x;
    const int lane = t & 31;
    const int w    = t >> 5;
    const int g    = lane >> 2;               // 0..7
    const int tq   = lane & 3;                // 0..3
    const int m0   = w * 16;
    const float scale = 0.08838834764831845f; // 1/sqrt(128)

    // ---- load Q tile (scaled, tf32): Qs[m][k], natural, coalesced ----
    const float* Qg = Q + (size_t)(qb * 128) * HID + h * HD;
    for (int idx = t; idx < 4096; idx += 256) {
        int m = idx >> 5, dv = (idx & 31) << 2;
        float4 v = *(const float4*)(Qg + (size_t)m * HID + dv);
        *(uint4*)(Qs + m * 132 + dv) =
            make_uint4(f2tf32(v.x * scale), f2tf32(v.y * scale),
                       f2tf32(v.z * scale), f2tf32(v.w * scale));
    }

    float oacc[16][4];
#pragma unroll
    for (int j = 0; j < 16; j++)
#pragma unroll
        for (int r = 0; r < 4; r++) oacc[j][r] = 0.f;
    float m_r[2] = {-1e30f, -1e30f};
    float l_r[2] = {0.f, 0.f};

    const int nkb = 2 * qb + 2;
    for (int kb = 0; kb < nkb; kb++) {
        __syncthreads();   // prev iter Ks/Vs consumption done (iter0: Qs fence part 1)

        // ---- load K,V tiles (tf32), natural layout, coalesced ----
        const float* Kg = K + (size_t)(kb * 64) * KVW + kvh * HD;
        const float* Vg = V + (size_t)(kb * 64) * KVW + kvh * HD;
        for (int idx = t; idx < 2048; idx += 256) {
            int n = idx >> 5, dv = (idx & 31) << 2;
            float4 vk = *(const float4*)(Kg + (size_t)n * KVW + dv);
            float4 vv = *(const float4*)(Vg + (size_t)n * KVW + dv);
            *(uint4*)(Ks + n * 132 + dv) =
                make_uint4(f2tf32(vk.x), f2tf32(vk.y), f2tf32(vk.z), f2tf32(vk.w));
            *(uint4*)(Vs + n * 132 + dv) =
                make_uint4(f2tf32(vv.x), f2tf32(vv.y), f2tf32(vv.z), f2tf32(vv.w));
        }
        __syncthreads();

        // ---- S = Q K^T : warp computes rows [m0, m0+16), all 64 kv cols ----
        float sacc[8][4];
#pragma unroll
        for (int j = 0; j < 8; j++)
#pragma unroll
            for (int r = 0; r < 4; r++) sacc[j][r] = 0.f;

#pragma unroll
        for (int ks = 0; ks < 16; ks++) {
            const int k0 = ks * 8;
            unsigned a0 = Qs[(m0 + g) * 132 + k0 + tq];
            unsigned a1 = Qs[(m0 + 8 + g) * 132 + k0 + tq];
            unsigned a2 = Qs[(m0 + g) * 132 + k0 + tq + 4];
            unsigned a3 = Qs[(m0 + 8 + g) * 132 + k0 + tq + 4];
#pragma unroll
            for (int j = 0; j < 8; j++) {
                unsigned b0 = Ks[(j * 8 + g) * 132 + k0 + tq];
                unsigned b1 = Ks[(j * 8 + g) * 132 + k0 + tq + 4];
                mma_tf32(sacc[j][0], sacc[j][1], sacc[j][2], sacc[j][3],
                         a0, a1, a2, a3, b0, b1);
            }
        }

        // ---- causal mask (only the two diagonal-overlapping tiles) ----
        const int rA = qb * 128 + m0 + g;
        const int rB = rA + 8;
        if (kb >= 2 * qb) {
#pragma unroll
            for (int j = 0; j < 8; j++) {
                int c = kb * 64 + j * 8 + 2 * tq;
                if (c     > rA) sacc[j][0] = -1e30f;
                if (c + 1 > rA) sacc[j][1] = -1e30f;
                if (c     > rB) sacc[j][2] = -1e30f;
                if (c + 1 > rB) sacc[j][3] = -1e30f;
            }
        }

        // ---- online softmax (rows g / g+8, shared by 4 lanes tq=0..3) ----
        float mA = -1e30f, mB = -1e30f;
#pragma unroll
        for (int j = 0; j < 8; j++) {
            mA = fmaxf(mA, fmaxf(sacc[j][0], sacc[j][1]));
            mB = fmaxf(mB, fmaxf(sacc[j][2], sacc[j][3]));
        }
        mA = fmaxf(mA, __shfl_xor_sync(0xffffffffu, mA, 1, 4));
        mA = fmaxf(mA, __shfl_xor_sync(0xffffffffu, mA, 2, 4));
        mB = fmaxf(mB, __shfl_xor_sync(0xffffffffu, mB, 1, 4));
        mB = fmaxf(mB, __shfl_xor_sync(0xffffffffu, mB, 2, 4));

        float mnA = fmaxf(m_r[0], mA);
        float mnB = fmaxf(m_r[1], mB);
        float corrA = __expf(m_r[0] - mnA);
        float corrB = __expf(m_r[1] - mnB);
        m_r[0] = mnA; m_r[1] = mnB;

        float sumA = 0.f, sumB = 0.f;
#pragma unroll
        for (int j = 0; j < 8; j++) {
            float p0 = __expf(sacc[j][0] - mnA);
            float p1 = __expf(sacc[j][1] - mnA);
            float p2 = __expf(sacc[j][2] - mnB);
            float p3 = __expf(sacc[j][3] - mnB);
            sumA += p0 + p1;
            sumB += p2 + p3;
            *(uint2*)(Ps + (m0 + g) * 68 + j * 8 + 2 * tq) =
                make_uint2(f2tf32(p0), f2tf32(p1));
            *(uint2*)(Ps + (m0 + 8 + g) * 68 + j * 8 + 2 * tq) =
                make_uint2(f2tf32(p2), f2tf32(p3));
        }
        sumA += __shfl_xor_sync(0xffffffffu, sumA, 1, 4);
        sumA += __shfl_xor_sync(0xffffffffu, sumA, 2, 4);
        sumB += __shfl_xor_sync(0xffffffffu, sumB, 1, 4);
        sumB += __shfl_xor_sync(0xffffffffu, sumB, 2, 4);
        l_r[0] = l_r[0] * corrA + sumA;
        l_r[1] = l_r[1] * corrB + sumB;

#pragma unroll
        for (int j = 0; j < 16; j++) {
            oacc[j][0] *= corrA; oacc[j][1] *= corrA;
            oacc[j][2] *= corrB; oacc[j][3] *= corrB;
        }
        __syncwarp();   // P visible to all lanes of this warp

        // ---- O += P V : warp rows [m0, m0+16), all 128 dims ----
#pragma unroll
        for (int ks = 0; ks < 8; ks++) {
            const int k0 = ks * 8;
            unsigned a0 = Ps[(m0 + g) * 68 + k0 + tq];
            unsigned a1 = Ps[(m0 + 8 + g) * 68 + k0 + tq];
            unsigned a2 = Ps[(m0 + g) * 68 + k0 + tq + 4];
            unsigned a3 = Ps[(m0 + 8 + g) * 68 + k0 + tq + 4];
#pragma unroll
            for (int j = 0; j < 16; j++) {
                unsigned b0 = Vs[(k0 + tq) * 132 + j * 8 + g];
                unsigned b1 = Vs[(k0 + tq + 4) * 132 + j * 8 + g];
                mma_tf32(oacc[j][0], oacc[j][1], oacc[j][2], oacc[j][3],
                         a0, a1, a2, a3, b0, b1);
            }
        }
    }

    // ---- epilogue: normalize, store to [token][h*128+dim] ----
    const float invA = 1.f / l_r[0];
    const float invB = 1.f / l_r[1];
    float* OgA = O + (size_t)(qb * 128 + m0 + g) * HID + h * HD;
    float* OgB = O + (size_t)(qb * 128 + m0 + 8 + g) * HID + h * HD;
#pragma unroll
    for (int j = 0; j < 16; j++) {
        int col = j * 8 + 2 * tq;
        *(float2*)(OgA + col) = make_float2(oacc[j][0] * invA, oacc[j][1] * invA);
        *(float2*)(OgB + col) = make_float2(oacc[j][2] * invB, oacc[j][3] * invB);
    }
}

// --------------------------------------------------------------------------
extern "C" void kernel_launch(void* const* d_in, const int* in_sizes, int n_in,
                              void* d_out, int out_size)
{
    const float* hs  = (const float*)d_in[0];
    // d_in[1] = attention_mask (pure causal; implemented directly, not read)
    const float* q_w = (const float*)d_in[2];
    const float* q_b = (const float*)d_in[3];
    const float* k_w = (const float*)d_in[4];
    const float* k_b = (const float*)d_in[5];
    const float* v_w = (const float*)d_in[6];
    const float* v_b = (const float*)d_in[7];
    const float* o_w = (const float*)d_in[8];
    float* out = (float*)d_out;
    (void)in_sizes; (void)n_in; (void)out_size;

    void *pq, *pk, *pv, *pa;
    cudaGetSymbolAddress(&pq, g_q);
    cudaGetSymbolAddress(&pk, g_k);
    cudaGetSymbolAddress(&pv, g_v);
    cudaGetSymbolAddress(&pa, g_attn);
    float* qf = (float*)pq;
    float* kf = (float*)pk;
    float* vf = (float*)pv;
    float* af = (float*)pa;

    cudaFuncSetAttribute(gemm_tf32_kernel,
                         cudaFuncAttributeMaxDynamicSharedMemorySize, GEMM_SMEM);
    cudaFuncSetAttribute(flash_tf32_kernel,
                         cudaFuncAttributeMaxDynamicSharedMemorySize, FL_SMEM);

    // 1. RoPE table
    rope_table_kernel<<<(S_LEN * 64 + 255) / 256, 256>>>();

    // 2. projections (NT: y = x @ W^T + b) on tensor pipe
    gemm_tf32_kernel<<<dim3(HID / 128, S_LEN / 128), 256, GEMM_SMEM>>>(
        hs, q_w, q_b, qf, S_LEN, HID, HID);
    gemm_tf32_kernel<<<dim3(KVW / 128, S_LEN / 128), 256, GEMM_SMEM>>>(
        hs, k_w, k_b, kf, S_LEN, KVW, HID);
    gemm_tf32_kernel<<<dim3(KVW / 128, S_LEN / 128), 256, GEMM_SMEM>>>(
        hs, v_w, v_b, vf, S_LEN, KVW, HID);

    // 3. RoPE on q and k
    rope_apply_kernel<<<(S_LEN * NH * 64 + 255) / 256, 256>>>(qf, NH, S_LEN * NH * 64);
    rope_apply_kernel<<<(S_LEN * NKV * 64 + 255) / 256, 256>>>(kf, NKV, S_LEN * NKV * 64);

    // 4. causal flash attention (GQA), tensor pipe
    flash_tf32_kernel<<<dim3(32, NH), 256, FL_SMEM>>>(qf, kf, vf, af);

    // 5. output projection
    gemm_tf32_kernel<<<dim3(HID / 128, S_LEN / 128), 256, GEMM_SMEM>>>(
        af, o_w, (const float*)nullptr, out, S_LEN, HID, HID);
}

// round 13
// speedup vs baseline: 2.6349x; 1.0007x over previous
#include <cuda_runtime.h>
#include <cuda_bf16.h>
#include <math.h>

// ===========================================================================
// Qwen2Attention  B=1 S=4096 HID=2048 NH=16 NKV=4 HD=128, RoPE theta=1e4
// R13: fused QKV projection + cp.async 3-stage pipelined tf32 GEMM.
// Flash attention (tf32 mma, warp-local softmax) unchanged from R12.
// ===========================================================================

#define S_LEN 4096
#define HID   2048
#define NH    16
#define NKV   4
#define HD    128
#define KVW   (NKV * HD)   // 512

// ----------------------------- scratch ------------------------------------
__device__ float g_q[S_LEN * HID];      // 32 MB
__device__ float g_k[S_LEN * KVW];      //  8 MB
__device__ float g_v[S_LEN * KVW];      //  8 MB
__device__ float g_attn[S_LEN * HID];   // 32 MB
__device__ float g_cos[S_LEN * (HD/2)];
__device__ float g_sin[S_LEN * (HD/2)];

// ----------------------- RoPE cos/sin table -------------------------------
__global__ void rope_table_kernel() {
    int idx = blockIdx.x * blockDim.x + threadIdx.x;
    if (idx >= S_LEN * (HD/2)) return;
    int d = idx & 63;
    int s = idx >> 6;
    double inv = 1.0 / pow(10000.0, (double)d / 64.0);
    double f = (double)s * inv;
    g_cos[idx] = (float)cos(f);
    g_sin[idx] = (float)sin(f);
}

// ----------------------- RoPE apply (in-place) ----------------------------
__global__ void rope_apply_kernel(float* __restrict__ x, int nheads, int total) {
    int idx = blockIdx.x * blockDim.x + threadIdx.x;
    if (idx >= total) return;
    int d = idx & 63;
    int h = (idx >> 6) % nheads;
    int s = idx / (64 * nheads);
    float c  = g_cos[s * 64 + d];
    float sn = g_sin[s * 64 + d];
    float* p = x + (size_t)s * (nheads * HD) + h * HD;
    float x1 = p[d];
    float x2 = p[d + 64];
    p[d]      = x1 * c - x2 * sn;
    p[d + 64] = x2 * c + x1 * sn;
}

// ------------------------- tf32 / async helpers ----------------------------
__device__ __forceinline__ unsigned f2tf32(float x) {
    unsigned r;
    asm("cvt.rna.tf32.f32 %0, %1;" : "=r"(r) : "f"(x));
    return r;
}
__device__ __forceinline__ unsigned u2tf32(unsigned xu) {
    unsigned r;
    asm("cvt.rna.tf32.f32 %0, %1;" : "=r"(r) : "f"(__uint_as_float(xu)));
    return r;
}

__device__ __forceinline__ void mma_tf32(
    float& c0, float& c1, float& c2, float& c3,
    unsigned a0, unsigned a1, unsigned a2, unsigned a3,
    unsigned b0, unsigned b1)
{
    asm volatile(
        "mma.sync.aligned.m16n8k8.row.col.f32.tf32.tf32.f32 "
        "{%0,%1,%2,%3}, {%4,%5,%6,%7}, {%8,%9}, {%0,%1,%2,%3};\n"
        : "+f"(c0), "+f"(c1), "+f"(c2), "+f"(c3)
        : "r"(a0), "r"(a1), "r"(a2), "r"(a3), "r"(b0), "r"(b1));
}

#define CP_ASYNC16(dst, src) \
    asm volatile("cp.async.cg.shared.global [%0], [%1], 16;\n" :: "r"(dst), "l"(src))
#define CP_COMMIT() asm volatile("cp.async.commit_group;\n" ::: "memory")
#define CP_WAIT1()  asm volatile("cp.async.wait_group 1;\n" ::: "memory")

// ------------------- pipelined tf32 NT GEMM core ---------------------------
// C[m][n] = sum_k A[m*2048+k]*B[n*2048+k] (+bias[n]); BM=BN=128, BK=32,
// 3-stage cp.async pipeline, raw fp32 in smem, cvt.rna at fragment load.
// 256 thr = 8 warps (4m x 2n), warp tile 32x64 via m16n8k8.
#define NSTAGE 3
#define BKW 36                              // 32 + 4 pad words per row
#define STAGE_WORDS (128 * BKW * 2)         // A + B
#define GEMM_SMEM (NSTAGE * STAGE_WORDS * 4)  // 110592 B

__device__ __forceinline__ void gemm_core(
    const float* __restrict__ A, const float* __restrict__ B,
    const float* __restrict__ bias, float* __restrict__ C,
    int N, int bm, int bn, unsigned* sm)
{
    const int K = 2048;
    const int t = threadIdx.x;
    const int lane = t & 31, warp = t >> 5;
    const int wm = warp >> 1, wn = warp & 1;
    const int g = lane >> 2, tq = lane & 3;
    const int lr = t >> 3;            // 0..31 (row within 32-row group)
    const int lc = (t & 7) << 2;      // 0,4,...,28

    const float* Ag = A + (size_t)(bm + lr) * K + lc;
    const float* Bg = B + (size_t)(bn + lr) * K + lc;
    const unsigned smem_base = (unsigned)__cvta_generic_to_shared(sm);

    float acc[2][8][4];
#pragma unroll
    for (int mi = 0; mi < 2; mi++)
#pragma unroll
        for (int j = 0; j < 8; j++)
#pragma unroll
            for (int r = 0; r < 4; r++) acc[mi][j][r] = 0.f;

    // issue tile kt into stage kt%NSTAGE (guarded copies, ALWAYS commit)
    auto issue_tile = [&](int kt) {
        if (kt < 64) {
            int st = kt % NSTAGE;
            unsigned abase = smem_base + st * STAGE_WORDS * 4;
            unsigned bbase = abase + 128 * BKW * 4;
            const float* Ap = Ag + (size_t)kt * 32;
            const float* Bp = Bg + (size_t)kt * 32;
#pragma unroll
            for (int i = 0; i < 4; i++) {
                unsigned off = ((lr + 32 * i) * BKW + lc) * 4;
                CP_ASYNC16(abase + off, Ap + (size_t)(32 * i) * K);
                CP_ASYNC16(bbase + off, Bp + (size_t)(32 * i) * K);
            }
        }
        CP_COMMIT();
    };

    issue_tile(0);
    issue_tile(1);

    for (int kt = 0; kt < 64; kt++) {
        CP_WAIT1();          // tile kt's group complete (<=1 newer pending)
        __syncthreads();     // data from ALL threads visible; prev consume done
        issue_tile(kt + 2);  // overwrites stage consumed at iter kt-1 (safe)

        const unsigned* As = sm + (kt % NSTAGE) * STAGE_WORDS;
        const unsigned* Bs = As + 128 * BKW;

#pragma unroll
        for (int ks = 0; ks < 4; ks++) {
            const int k0 = ks * 8;
            unsigned a[2][4];
#pragma unroll
            for (int mi = 0; mi < 2; mi++) {
                const unsigned* ap = As + (wm * 32 + mi * 16 + g) * BKW + k0 + tq;
                a[mi][0] = u2tf32(ap[0]);
                a[mi][2] = u2tf32(ap[4]);
                a[mi][1] = u2tf32(ap[8 * BKW]);
                a[mi][3] = u2tf32(ap[8 * BKW + 4]);
            }
#pragma unroll
            for (int j = 0; j < 8; j++) {
                const unsigned* bp = Bs + (wn * 64 + j * 8 + g) * BKW + k0 + tq;
                unsigned b0 = u2tf32(bp[0]);
                unsigned b1 = u2tf32(bp[4]);
#pragma unroll
                for (int mi = 0; mi < 2; mi++)
                    mma_tf32(acc[mi][j][0], acc[mi][j][1], acc[mi][j][2], acc[mi][j][3],
                             a[mi][0], a[mi][1], a[mi][2], a[mi][3], b0, b1);
            }
        }
        // no trailing sync: next iter's top sync protects stage reuse
    }

    // ---- epilogue: bias + store ----
#pragma unroll
    for (int mi = 0; mi < 2; mi++) {
        int row = bm + wm * 32 + mi * 16 + g;
#pragma unroll
        for (int j = 0; j < 8; j++) {
            int col = bn + wn * 64 + j * 8 + 2 * tq;
            float b0 = 0.f, b1 = 0.f;
            if (bias) { b0 = bias[col]; b1 = bias[col + 1]; }
            *(float2*)(C + (size_t)row * N + col) =
                make_float2(acc[mi][j][0] + b0, acc[mi][j][1] + b1);
            *(float2*)(C + (size_t)(row + 8) * N + col) =
                make_float2(acc[mi][j][2] + b0, acc[mi][j][3] + b1);
        }
    }
}

// fused QKV projection: grid (24, 32). x<16 -> Q, x<20 -> K, else V.
__global__ __launch_bounds__(256, 2) void qkv_kernel(
    const float* __restrict__ hs,
    const float* __restrict__ qw, const float* __restrict__ qb,
    const float* __restrict__ kw, const float* __restrict__ kb,
    const float* __restrict__ vw, const float* __restrict__ vb)
{
    extern __shared__ unsigned smu[];
    const int bx = blockIdx.x;
    const int bm = blockIdx.y << 7;
    if (bx < 16)      gemm_core(hs, qw, qb, g_q, HID, bm, bx << 7, smu);
    else if (bx < 20) gemm_core(hs, kw, kb, g_k, KVW, bm, (bx - 16) << 7, smu);
    else              gemm_core(hs, vw, vb, g_v, KVW, bm, (bx - 20) << 7, smu);
}

// generic single GEMM (O projection): grid (N/128, 32)
__global__ __launch_bounds__(256, 2) void gemm_kernel(
    const float* __restrict__ A, const float* __restrict__ B,
    const float* __restrict__ bias, float* __restrict__ C, int N)
{
    extern __shared__ unsigned smu[];
    gemm_core(A, B, bias, C, N, blockIdx.y << 7, blockIdx.x << 7, smu);
}

// --------------------- flash attention (tf32 tensor) ------------------------
// grid (32, 16): x -> q tile of 128 rows (reversed), y -> head.
// 256 threads = 8 warps; warp w owns rows [w*16, w*16+16) -> softmax warp-local.
#define FL_SMEM ((128*132 + 64*132 + 64*132 + 128*68) * 4)   // 169984 B

__global__ __launch_bounds__(256, 1) void flash_tf32_kernel(
    const float* __restrict__ Q, const float* __restrict__ K,
    const float* __restrict__ V, float* __restrict__ O)
{
    extern __shared__ unsigned fsm[];
    unsigned* Qs = fsm;                       // [128][132]
    unsigned* Ks = Qs + 128 * 132;            // [64][132]
    unsigned* Vs = Ks + 64 * 132;             // [64][132]
    unsigned* Ps = Vs + 64 * 132;             // [128][68]

    const int h   = blockIdx.y;
    const int qb  = 31 - (int)blockIdx.x;     // big tiles first
    const int kvh = h >> 2;                   // GQA group of 4
    const int t    = threadIdx.x;
    const int lane = t & 31;
    const int w    = t >> 5;
    const int g    = lane >> 2;               // 0..7
    const int tq   = lane & 3;                // 0..3
    const int m0   = w * 16;
    const float scale = 0.08838834764831845f; // 1/sqrt(128)

    const float* Qg = Q + (size_t)(qb * 128) * HID + h * HD;
    for (int idx = t; idx < 4096; idx += 256) {
        int m = idx >> 5, dv = (idx & 31) << 2;
        float4 v = *(const float4*)(Qg + (size_t)m * HID + dv);
        *(uint4*)(Qs + m * 132 + dv) =
            make_uint4(f2tf32(v.x * scale), f2tf32(v.y * scale),
                       f2tf32(v.z * scale), f2tf32(v.w * scale));
    }

    float oacc[16][4];
#pragma unroll
    for (int j = 0; j < 16; j++)
#pragma unroll
        for (int r = 0; r < 4; r++) oacc[j][r] = 0.f;
    float m_r[2] = {-1e30f, -1e30f};
    float l_r[2] = {0.f, 0.f};

    const int nkb = 2 * qb + 2;
    for (int kb = 0; kb < nkb; kb++) {
        __syncthreads();

        const float* Kg = K + (size_t)(kb * 64) * KVW + kvh * HD;
        const float* Vg = V + (size_t)(kb * 64) * KVW + kvh * HD;
        for (int idx = t; idx < 2048; idx += 256) {
            int n = idx >> 5, dv = (idx & 31) << 2;
            float4 vk = *(const float4*)(Kg + (size_t)n * KVW + dv);
            float4 vv = *(const float4*)(Vg + (size_t)n * KVW + dv);
            *(uint4*)(Ks + n * 132 + dv) =
                make_uint4(f2tf32(vk.x), f2tf32(vk.y), f2tf32(vk.z), f2tf32(vk.w));
            *(uint4*)(Vs + n * 132 + dv) =
                make_uint4(f2tf32(vv.x), f2tf32(vv.y), f2tf32(vv.z), f2tf32(vv.w));
        }
        __syncthreads();

        float sacc[8][4];
#pragma unroll
        for (int j = 0; j < 8; j++)
#pragma unroll
            for (int r = 0; r < 4; r++) sacc[j][r] = 0.f;

#pragma unroll
        for (int ks = 0; ks < 16; ks++) {
            const int k0 = ks * 8;
            unsigned a0 = Qs[(m0 + g) * 132 + k0 + tq];
            unsigned a1 = Qs[(m0 + 8 + g) * 132 + k0 + tq];
            unsigned a2 = Qs[(m0 + g) * 132 + k0 + tq + 4];
            unsigned a3 = Qs[(m0 + 8 + g) * 132 + k0 + tq + 4];
#pragma unroll
            for (int j = 0; j < 8; j++) {
                unsigned b0 = Ks[(j * 8 + g) * 132 + k0 + tq];
                unsigned b1 = Ks[(j * 8 + g) * 132 + k0 + tq + 4];
                mma_tf32(sacc[j][0], sacc[j][1], sacc[j][2], sacc[j][3],
                         a0, a1, a2, a3, b0, b1);
            }
        }

        const int rA = qb * 128 + m0 + g;
        const int rB = rA + 8;
        if (kb >= 2 * qb) {
#pragma unroll
            for (int j = 0; j < 8; j++) {
                int c = kb * 64 + j * 8 + 2 * tq;
                if (c     > rA) sacc[j][0] = -1e30f;
                if (c + 1 > rA) sacc[j][1] = -1e30f;
                if (c     > rB) sacc[j][2] = -1e30f;
                if (c + 1 > rB) sacc[j][3] = -1e30f;
            }
        }

        float mA = -1e30f, mB = -1e30f;
#pragma unroll
        for (int j = 0; j < 8; j++) {
            mA = fmaxf(mA, fmaxf(sacc[j][0], sacc[j][1]));
            mB = fmaxf(mB, fmaxf(sacc[j][2], sacc[j][3]));
        }
        mA = fmaxf(mA, __shfl_xor_sync(0xffffffffu, mA, 1, 4));
        mA = fmaxf(mA, __shfl_xor_sync(0xffffffffu, mA, 2, 4));
        mB = fmaxf(mB, __shfl_xor_sync(0xffffffffu, mB, 1, 4));
        mB = fmaxf(mB, __shfl_xor_sync(0xffffffffu, mB, 2, 4));

        float mnA = fmaxf(m_r[0], mA);
        float mnB = fmaxf(m_r[1], mB);
        float corrA = __expf(m_r[0] - mnA);
        float corrB = __expf(m_r[1] - mnB);
        m_r[0] = mnA; m_r[1] = mnB;

        float sumA = 0.f, sumB = 0.f;
#pragma unroll
        for (int j = 0; j < 8; j++) {
            float p0 = __expf(sacc[j][0] - mnA);
            float p1 = __expf(sacc[j][1] - mnA);
            float p2 = __expf(sacc[j][2] - mnB);
            float p3 = __expf(sacc[j][3] - mnB);
            sumA += p0 + p1;
            sumB += p2 + p3;
            *(uint2*)(Ps + (m0 + g) * 68 + j * 8 + 2 * tq) =
                make_uint2(f2tf32(p0), f2tf32(p1));
            *(uint2*)(Ps + (m0 + 8 + g) * 68 + j * 8 + 2 * tq) =
                make_uint2(f2tf32(p2), f2tf32(p3));
        }
        sumA += __shfl_xor_sync(0xffffffffu, sumA, 1, 4);
        sumA += __shfl_xor_sync(0xffffffffu, sumA, 2, 4);
        sumB += __shfl_xor_sync(0xffffffffu, sumB, 1, 4);
        sumB += __shfl_xor_sync(0xffffffffu, sumB, 2, 4);
        l_r[0] = l_r[0] * corrA + sumA;
        l_r[1] = l_r[1] * corrB + sumB;

#pragma unroll
        for (int j = 0; j < 16; j++) {
            oacc[j][0] *= corrA; oacc[j][1] *= corrA;
            oacc[j][2] *= corrB; oacc[j][3] *= corrB;
        }
        __syncwarp();

#pragma unroll
        for (int ks = 0; ks < 8; ks++) {
            const int k0 = ks * 8;
            unsigned a0 = Ps[(m0 + g) * 68 + k0 + tq];
            unsigned a1 = Ps[(m0 + 8 + g) * 68 + k0 + tq];
            unsigned a2 = Ps[(m0 + g) * 68 + k0 + tq + 4];
            unsigned a3 = Ps[(m0 + 8 + g) * 68 + k0 + tq + 4];
#pragma unroll
            for (int j = 0; j < 16; j++) {
                unsigned b0 = Vs[(k0 + tq) * 132 + j * 8 + g];
                unsigned b1 = Vs[(k0 + tq + 4) * 132 + j * 8 + g];
                mma_tf32(oacc[j][0], oacc[j][1], oacc[j][2], oacc[j][3],
                         a0, a1, a2, a3, b0, b1);
            }
        }
    }

    const float invA = 1.f / l_r[0];
    const float invB = 1.f / l_r[1];
    float* OgA = O + (size_t)(qb * 128 + m0 + g) * HID + h * HD;
    float* OgB = O + (size_t)(qb * 128 + m0 + 8 + g) * HID + h * HD;
#pragma unroll
    for (int j = 0; j < 16; j++) {
        int col = j * 8 + 2 * tq;
        *(float2*)(OgA + col) = make_float2(oacc[j][0] * invA, oacc[j][1] * invA);
        *(float2*)(OgB + col) = make_float2(oacc[j][2] * invB, oacc[j][3] * invB);
    }
}

// --------------------------------------------------------------------------
extern "C" void kernel_launch(void* const* d_in, const int* in_sizes, int n_in,
                              void* d_out, int out_size)
{
    const float* hs  = (const float*)d_in[0];
    // d_in[1] = attention_mask (pure causal; implemented directly, not read)
    const float* q_w = (const float*)d_in[2];
    const float* q_b = (const float*)d_in[3];
    const float* k_w = (const float*)d_in[4];
    const float* k_b = (const float*)d_in[5];
    const float* v_w = (const float*)d_in[6];
    const float* v_b = (const float*)d_in[7];
    const float* o_w = (const float*)d_in[8];
    float* out = (float*)d_out;
    (void)in_sizes; (void)n_in; (void)out_size;

    void *pq, *pk, *pv, *pa;
    cudaGetSymbolAddress(&pq, g_q);
    cudaGetSymbolAddress(&pk, g_k);
    cudaGetSymbolAddress(&pv, g_v);
    cudaGetSymbolAddress(&pa, g_attn);
    float* qf = (float*)pq;
    float* kf = (float*)pk;
    float* vf = (float*)pv;
    float* af = (float*)pa;

    cudaFuncSetAttribute(qkv_kernel,
                         cudaFuncAttributeMaxDynamicSharedMemorySize, GEMM_SMEM);
    cudaFuncSetAttribute(gemm_kernel,
                         cudaFuncAttributeMaxDynamicSharedMemorySize, GEMM_SMEM);
    cudaFuncSetAttribute(flash_tf32_kernel,
                         cudaFuncAttributeMaxDynamicSharedMemorySize, FL_SMEM);

    // 1. RoPE table
    rope_table_kernel<<<(S_LEN * 64 + 255) / 256, 256>>>();

    // 2. fused Q/K/V projections (tensor pipe, pipelined)
    qkv_kernel<<<dim3(24, S_LEN / 128), 256, GEMM_SMEM>>>(
        hs, q_w, q_b, k_w, k_b, v_w, v_b);

    // 3. RoPE on q and k
    rope_apply_kernel<<<(S_LEN * NH * 64 + 255) / 256, 256>>>(qf, NH, S_LEN * NH * 64);
    rope_apply_kernel<<<(S_LEN * NKV * 64 + 255) / 256, 256>>>(kf, NKV, S_LEN * NKV * 64);

    // 4. causal flash attention (GQA), tensor pipe
    flash_tf32_kernel<<<dim3(32, NH), 256, FL_SMEM>>>(qf, kf, vf, af);

    // 5. output projection
    gemm_kernel<<<dim3(HID / 128, S_LEN / 128), 256, GEMM_SMEM>>>(
        af, o_w, (const float*)nullptr, out, HID);
}

// round 17
// speedup vs baseline: 2.7008x; 1.0250x over previous
#include <cuda_runtime.h>
#include <cuda_bf16.h>
#include <math.h>

// ===========================================================================
// Qwen2Attention  B=1 S=4096 HID=2048 NH=16 NKV=4 HD=128, RoPE theta=1e4
// R14: pre-convert inputs/weights to tf32 once; GEMM inner loop is pure
// LDS+mma (cp.async 3-stage). Flash epilogue writes tf32-rounded attn so the
// O-projection is also cvt-free. Flash mainloop unchanged from R12.
// ===========================================================================

#define S_LEN 4096
#define HID   2048
#define NH    16
#define NKV   4
#define HD    128
#define KVW   (NKV * HD)   // 512

// ----------------------------- scratch ------------------------------------
__device__ float g_q[S_LEN * HID];      // 32 MB
__device__ float g_k[S_LEN * KVW];      //  8 MB
__device__ float g_v[S_LEN * KVW];      //  8 MB
__device__ float g_attn[S_LEN * HID];   // 32 MB (tf32-rounded by flash)
__device__ float g_cos[S_LEN * (HD/2)];
__device__ float g_sin[S_LEN * (HD/2)];
// pre-converted (tf32-rounded fp32) operands
__device__ float g_hs_t[S_LEN * HID];   // 32 MB
__device__ float g_qw_t[HID * HID];     // 16 MB
__device__ float g_kw_t[KVW * HID];     //  4 MB
__device__ float g_vw_t[KVW * HID];     //  4 MB
__device__ float g_ow_t[HID * HID];     // 16 MB

// ------------------------- tf32 helpers ------------------------------------
__device__ __forceinline__ unsigned f2tf32(float x) {
    unsigned r;
    asm("cvt.rna.tf32.f32 %0, %1;" : "=r"(r) : "f"(x));
    return r;
}

__device__ __forceinline__ void mma_tf32(
    float& c0, float& c1, float& c2, float& c3,
    unsigned a0, unsigned a1, unsigned a2, unsigned a3,
    unsigned b0, unsigned b1)
{
    asm volatile(
        "mma.sync.aligned.m16n8k8.row.col.f32.tf32.tf32.f32 "
        "{%0,%1,%2,%3}, {%4,%5,%6,%7}, {%8,%9}, {%0,%1,%2,%3};\n"
        : "+f"(c0), "+f"(c1), "+f"(c2), "+f"(c3)
        : "r"(a0), "r"(a1), "r"(a2), "r"(a3), "r"(b0), "r"(b1));
}

// ----------------------- tf32 pre-convert (elementwise) ---------------------
__global__ void cvt_tf32_kernel(const float* __restrict__ src,
                                float* __restrict__ dst, int n4) {
    int i = blockIdx.x * blockDim.x + threadIdx.x;
    if (i >= n4) return;
    float4 v = ((const float4*)src)[i];
    uint4 u = make_uint4(f2tf32(v.x), f2tf32(v.y), f2tf32(v.z), f2tf32(v.w));
    ((uint4*)dst)[i] = u;
}

// ----------------------- RoPE cos/sin table -------------------------------
__global__ void rope_table_kernel() {
    int idx = blockIdx.x * blockDim.x + threadIdx.x;
    if (idx >= S_LEN * (HD/2)) return;
    int d = idx & 63;
    int s = idx >> 6;
    double inv = 1.0 / pow(10000.0, (double)d / 64.0);
    double f = (double)s * inv;
    g_cos[idx] = (float)cos(f);
    g_sin[idx] = (float)sin(f);
}

// ----------------------- RoPE apply (in-place) ----------------------------
__global__ void rope_apply_kernel(float* __restrict__ x, int nheads, int total) {
    int idx = blockIdx.x * blockDim.x + threadIdx.x;
    if (idx >= total) return;
    int d = idx & 63;
    int h = (idx >> 6) % nheads;
    int s = idx / (64 * nheads);
    float c  = g_cos[s * 64 + d];
    float sn = g_sin[s * 64 + d];
    float* p = x + (size_t)s * (nheads * HD) + h * HD;
    float x1 = p[d];
    float x2 = p[d + 64];
    p[d]      = x1 * c - x2 * sn;
    p[d + 64] = x2 * c + x1 * sn;
}

// ------------------------- async copy helpers ------------------------------
#define CP_ASYNC16(dst, src) \
    asm volatile("cp.async.cg.shared.global [%0], [%1], 16;\n" :: "r"(dst), "l"(src))
#define CP_COMMIT() asm volatile("cp.async.commit_group;\n" ::: "memory")
#define CP_WAIT1()  asm volatile("cp.async.wait_group 1;\n" ::: "memory")

// ------------------- pipelined tf32 NT GEMM core ---------------------------
// Inputs A,B PRE-ROUNDED to tf32. C[m][n] = sum_k A[m*2048+k]*B[n*2048+k]
// (+bias[n]); BM=BN=128, BK=32, 3-stage cp.async, inner loop pure LDS+mma.
#define NSTAGE 3
#define BKW 36                              // 32 + 4 pad words per row
#define STAGE_WORDS (128 * BKW * 2)         // A + B
#define GEMM_SMEM (NSTAGE * STAGE_WORDS * 4)  // 110592 B

__device__ __forceinline__ void gemm_core(
    const float* __restrict__ A, const float* __restrict__ B,
    const float* __restrict__ bias, float* __restrict__ C,
    int N, int bm, int bn, unsigned* sm)
{
    const int K = 2048;
    const int t = threadIdx.x;
    const int lane = t & 31, warp = t >> 5;
    const int wm = warp >> 1, wn = warp & 1;
    const int g = lane >> 2, tq = lane & 3;
    const int lr = t >> 3;            // 0..31
    const int lc = (t & 7) << 2;      // 0,4,...,28

    const float* Ag = A + (size_t)(bm + lr) * K + lc;
    const float* Bg = B + (size_t)(bn + lr) * K + lc;
    const unsigned smem_base = (unsigned)__cvta_generic_to_shared(sm);

    float acc[2][8][4];
#pragma unroll
    for (int mi = 0; mi < 2; mi++)
#pragma unroll
        for (int j = 0; j < 8; j++)
#pragma unroll
            for (int r = 0; r < 4; r++) acc[mi][j][r] = 0.f;

    auto issue_tile = [&](int kt) {
        if (kt < 64) {
            int st = kt % NSTAGE;
            unsigned abase = smem_base + st * STAGE_WORDS * 4;
            unsigned bbase = abase + 128 * BKW * 4;
            const float* Ap = Ag + (size_t)kt * 32;
            const float* Bp = Bg + (size_t)kt * 32;
#pragma unroll
            for (int i = 0; i < 4; i++) {
                unsigned off = ((lr + 32 * i) * BKW + lc) * 4;
                CP_ASYNC16(abase + off, Ap + (size_t)(32 * i) * K);
                CP_ASYNC16(bbase + off, Bp + (size_t)(32 * i) * K);
            }
        }
        CP_COMMIT();
    };

    issue_tile(0);
    issue_tile(1);

    for (int kt = 0; kt < 64; kt++) {
        CP_WAIT1();
        __syncthreads();
        issue_tile(kt + 2);

        const unsigned* As = sm + (kt % NSTAGE) * STAGE_WORDS;
        const unsigned* Bs = As + 128 * BKW;

#pragma unroll
        for (int ks = 0; ks < 4; ks++) {
            const int k0 = ks * 8;
            unsigned a[2][4];
#pragma unroll
            for (int mi = 0; mi < 2; mi++) {
                const unsigned* ap = As + (wm * 32 + mi * 16 + g) * BKW + k0 + tq;
                a[mi][0] = ap[0];
                a[mi][2] = ap[4];
                a[mi][1] = ap[8 * BKW];
                a[mi][3] = ap[8 * BKW + 4];
            }
#pragma unroll
            for (int j = 0; j < 8; j++) {
                const unsigned* bp = Bs + (wn * 64 + j * 8 + g) * BKW + k0 + tq;
                unsigned b0 = bp[0];
                unsigned b1 = bp[4];
#pragma unroll
                for (int mi = 0; mi < 2; mi++)
                    mma_tf32(acc[mi][j][0], acc[mi][j][1], acc[mi][j][2], acc[mi][j][3],
                             a[mi][0], a[mi][1], a[mi][2], a[mi][3], b0, b1);
            }
        }
    }

    // ---- epilogue: bias + store ----
#pragma unroll
    for (int mi = 0; mi < 2; mi++) {
        int row = bm + wm * 32 + mi * 16 + g;
#pragma unroll
        for (int j = 0; j < 8; j++) {
            int col = bn + wn * 64 + j * 8 + 2 * tq;
            float b0 = 0.f, b1 = 0.f;
            if (bias) { b0 = bias[col]; b1 = bias[col + 1]; }
            *(float2*)(C + (size_t)row * N + col) =
                make_float2(acc[mi][j][0] + b0, acc[mi][j][1] + b1);
            *(float2*)(C + (size_t)(row + 8) * N + col) =
                make_float2(acc[mi][j][2] + b0, acc[mi][j][3] + b1);
        }
    }
}

// fused QKV projection: grid (24, 32). x<16 -> Q, x<20 -> K, else V.
__global__ __launch_bounds__(256, 2) void qkv_kernel(
    const float* __restrict__ qb_, const float* __restrict__ kb_,
    const float* __restrict__ vb_)
{
    extern __shared__ unsigned smu[];
    const int bx = blockIdx.x;
    const int bm = blockIdx.y << 7;
    if (bx < 16)      gemm_core(g_hs_t, g_qw_t, qb_, g_q, HID, bm, bx << 7, smu);
    else if (bx < 20) gemm_core(g_hs_t, g_kw_t, kb_, g_k, KVW, bm, (bx - 16) << 7, smu);
    else              gemm_core(g_hs_t, g_vw_t, vb_, g_v, KVW, bm, (bx - 20) << 7, smu);
}

// O projection: grid (16, 32)
__global__ __launch_bounds__(256, 2) void oproj_kernel(float* __restrict__ out)
{
    extern __shared__ unsigned smu[];
    gemm_core(g_attn, g_ow_t, (const float*)0, out, HID,
              blockIdx.y << 7, blockIdx.x << 7, smu);
}

// --------------------- flash attention (tf32 tensor) ------------------------
// grid (32, 16): x -> q tile of 128 rows (reversed), y -> head.
// 256 threads = 8 warps; warp w owns rows [w*16, w*16+16) -> softmax warp-local.
#define FL_SMEM ((128*132 + 64*132 + 64*132 + 128*68) * 4)   // 169984 B

__global__ __launch_bounds__(256, 1) void flash_tf32_kernel(
    const float* __restrict__ Q, const float* __restrict__ K,
    const float* __restrict__ V, float* __restrict__ O)
{
    extern __shared__ unsigned fsm[];
    unsigned* Qs = fsm;                       // [128][132]
    unsigned* Ks = Qs + 128 * 132;            // [64][132]
    unsigned* Vs = Ks + 64 * 132;             // [64][132]
    unsigned* Ps = Vs + 64 * 132;             // [128][68]

    const int h   = blockIdx.y;
    const int qb  = 31 - (int)blockIdx.x;     // big tiles first
    const int kvh = h >> 2;                   // GQA group of 4
    const int t    = threadIdx.x;
    const int lane = t & 31;
    const int w    = t >> 5;
    const int g    = lane >> 2;               // 0..7
    const int tq   = lane & 3;                // 0..3
    const int m0   = w * 16;
    const float scale = 0.08838834764831845f; // 1/sqrt(128)

    const float* Qg = Q + (size_t)(qb * 128) * HID + h * HD;
    for (int idx = t; idx < 4096; idx += 256) {
        int m = idx >> 5, dv = (idx & 31) << 2;
        float4 v = *(const float4*)(Qg + (size_t)m * HID + dv);
        *(uint4*)(Qs + m * 132 + dv) =
            make_uint4(f2tf32(v.x * scale), f2tf32(v.y * scale),
                       f2tf32(v.z * scale), f2tf32(v.w * scale));
    }

    float oacc[16][4];
#pragma unroll
    for (int j = 0; j < 16; j++)
#pragma unroll
        for (int r = 0; r < 4; r++) oacc[j][r] = 0.f;
    float m_r[2] = {-1e30f, -1e30f};
    float l_r[2] = {0.f, 0.f};

    const int nkb = 2 * qb + 2;
    for (int kb = 0; kb < nkb; kb++) {
        __syncthreads();

        const float* Kg = K + (size_t)(kb * 64) * KVW + kvh * HD;
        const float* Vg = V + (size_t)(kb * 64) * KVW + kvh * HD;
        for (int idx = t; idx < 2048; idx += 256) {
            int n = idx >> 5, dv = (idx & 31) << 2;
            float4 vk = *(const float4*)(Kg + (size_t)n * KVW + dv);
            float4 vv = *(const float4*)(Vg + (size_t)n * KVW + dv);
            *(uint4*)(Ks + n * 132 + dv) =
                make_uint4(f2tf32(vk.x), f2tf32(vk.y), f2tf32(vk.z), f2tf32(vk.w));
            *(uint4*)(Vs + n * 132 + dv) =
                make_uint4(f2tf32(vv.x), f2tf32(vv.y), f2tf32(vv.z), f2tf32(vv.w));
        }
        __syncthreads();

        float sacc[8][4];
#pragma unroll
        for (int j = 0; j < 8; j++)
#pragma unroll
            for (int r = 0; r < 4; r++) sacc[j][r] = 0.f;

#pragma unroll
        for (int ks = 0; ks < 16; ks++) {
            const int k0 = ks * 8;
            unsigned a0 = Qs[(m0 + g) * 132 + k0 + tq];
            unsigned a1 = Qs[(m0 + 8 + g) * 132 + k0 + tq];
            unsigned a2 = Qs[(m0 + g) * 132 + k0 + tq + 4];
            unsigned a3 = Qs[(m0 + 8 + g) * 132 + k0 + tq + 4];
#pragma unroll
            for (int j = 0; j < 8; j++) {
                unsigned b0 = Ks[(j * 8 + g) * 132 + k0 + tq];
                unsigned b1 = Ks[(j * 8 + g) * 132 + k0 + tq + 4];
                mma_tf32(sacc[j][0], sacc[j][1], sacc[j][2], sacc[j][3],
                         a0, a1, a2, a3, b0, b1);
            }
        }

        const int rA = qb * 128 + m0 + g;
        const int rB = rA + 8;
        if (kb >= 2 * qb) {
#pragma unroll
            for (int j = 0; j < 8; j++) {
                int c = kb * 64 + j * 8 + 2 * tq;
                if (c     > rA) sacc[j][0] = -1e30f;
                if (c + 1 > rA) sacc[j][1] = -1e30f;
                if (c     > rB) sacc[j][2] = -1e30f;
                if (c + 1 > rB) sacc[j][3] = -1e30f;
            }
        }

        float mA = -1e30f, mB = -1e30f;
#pragma unroll
        for (int j = 0; j < 8; j++) {
            mA = fmaxf(mA, fmaxf(sacc[j][0], sacc[j][1]));
            mB = fmaxf(mB, fmaxf(sacc[j][2], sacc[j][3]));
        }
        mA = fmaxf(mA, __shfl_xor_sync(0xffffffffu, mA, 1, 4));
        mA = fmaxf(mA, __shfl_xor_sync(0xffffffffu, mA, 2, 4));
        mB = fmaxf(mB, __shfl_xor_sync(0xffffffffu, mB, 1, 4));
        mB = fmaxf(mB, __shfl_xor_sync(0xffffffffu, mB, 2, 4));

        float mnA = fmaxf(m_r[0], mA);
        float mnB = fmaxf(m_r[1], mB);
        float corrA = __expf(m_r[0] - mnA);
        float corrB = __expf(m_r[1] - mnB);
        m_r[0] = mnA; m_r[1] = mnB;

        float sumA = 0.f, sumB = 0.f;
#pragma unroll
        for (int j = 0; j < 8; j++) {
            float p0 = __expf(sacc[j][0] - mnA);
            float p1 = __expf(sacc[j][1] - mnA);
            float p2 = __expf(sacc[j][2] - mnB);
            float p3 = __expf(sacc[j][3] - mnB);
            sumA += p0 + p1;
            sumB += p2 + p3;
            *(uint2*)(Ps + (m0 + g) * 68 + j * 8 + 2 * tq) =
                make_uint2(f2tf32(p0), f2tf32(p1));
            *(uint2*)(Ps + (m0 + 8 + g) * 68 + j * 8 + 2 * tq) =
                make_uint2(f2tf32(p2), f2tf32(p3));
        }
        sumA += __shfl_xor_sync(0xffffffffu, sumA, 1, 4);
        sumA += __shfl_xor_sync(0xffffffffu, sumA, 2, 4);
        sumB += __shfl_xor_sync(0xffffffffu, sumB, 1, 4);
        sumB += __shfl_xor_sync(0xffffffffu, sumB, 2, 4);
        l_r[0] = l_r[0] * corrA + sumA;
        l_r[1] = l_r[1] * corrB + sumB;

#pragma unroll
        for (int j = 0; j < 16; j++) {
            oacc[j][0] *= corrA; oacc[j][1] *= corrA;
            oacc[j][2] *= corrB; oacc[j][3] *= corrB;
        }
        __syncwarp();

#pragma unroll
        for (int ks = 0; ks < 8; ks++) {
            const int k0 = ks * 8;
            unsigned a0 = Ps[(m0 + g) * 68 + k0 + tq];
            unsigned a1 = Ps[(m0 + 8 + g) * 68 + k0 + tq];
            unsigned a2 = Ps[(m0 + g) * 68 + k0 + tq + 4];
            unsigned a3 = Ps[(m0 + 8 + g) * 68 + k0 + tq + 4];
#pragma unroll
            for (int j = 0; j < 16; j++) {
                unsigned b0 = Vs[(k0 + tq) * 132 + j * 8 + g];
                unsigned b1 = Vs[(k0 + tq + 4) * 132 + j * 8 + g];
                mma_tf32(oacc[j][0], oacc[j][1], oacc[j][2], oacc[j][3],
                         a0, a1, a2, a3, b0, b1);
            }
        }
    }

    // epilogue: normalize + tf32-round (O-proj consumes without cvt)
    const float invA = 1.f / l_r[0];
    const float invB = 1.f / l_r[1];
    float* OgA = O + (size_t)(qb * 128 + m0 + g) * HID + h * HD;
    float* OgB = O + (size_t)(qb * 128 + m0 + 8 + g) * HID + h * HD;
#pragma unroll
    for (int j = 0; j < 16; j++) {
        int col = j * 8 + 2 * tq;
        *(uint2*)(OgA + col) = make_uint2(f2tf32(oacc[j][0] * invA),
                                          f2tf32(oacc[j][1] * invA));
        *(uint2*)(OgB + col) = make_uint2(f2tf32(oacc[j][2] * invB),
                                          f2tf32(oacc[j][3] * invB));
    }
}

// --------------------------------------------------------------------------
extern "C" void kernel_launch(void* const* d_in, const int* in_sizes, int n_in,
                              void* d_out, int out_size)
{
    const float* hs  = (const float*)d_in[0];
    // d_in[1] = attention_mask (pure causal; implemented directly, not read)
    const float* q_w = (const float*)d_in[2];
    const float* q_b = (const float*)d_in[3];
    const float* k_w = (const float*)d_in[4];
    const float* k_b = (const float*)d_in[5];
    const float* v_w = (const float*)d_in[6];
    const float* v_b = (const float*)d_in[7];
    const float* o_w = (const float*)d_in[8];
    float* out = (float*)d_out;
    (void)in_sizes; (void)n_in; (void)out_size;

    void *pq, *pk, *pv, *pa;
    void *pht, *pqt, *pkt, *pvt, *pot;
    cudaGetSymbolAddress(&pq, g_q);
    cudaGetSymbolAddress(&pk, g_k);
    cudaGetSymbolAddress(&pv, g_v);
    cudaGetSymbolAddress(&pa, g_attn);
    cudaGetSymbolAddress(&pht, g_hs_t);
    cudaGetSymbolAddress(&pqt, g_qw_t);
    cudaGetSymbolAddress(&pkt, g_kw_t);
    cudaGetSymbolAddress(&pvt, g_vw_t);
    cudaGetSymbolAddress(&pot, g_ow_t);
    float* qf = (float*)pq;
    float* kf = (float*)pk;
    float* vf = (float*)pv;
    float* af = (float*)pa;

    cudaFuncSetAttribute(qkv_kernel,
                         cudaFuncAttributeMaxDynamicSharedMemorySize, GEMM_SMEM);
    cudaFuncSetAttribute(oproj_kernel,
                         cudaFuncAttributeMaxDynamicSharedMemorySize, GEMM_SMEM);
    cudaFuncSetAttribute(flash_tf32_kernel,
                         cudaFuncAttributeMaxDynamicSharedMemorySize, FL_SMEM);

    // 0. pre-convert activations + weights to tf32 (rounded-once)
    {
        int n4;
        n4 = (S_LEN * HID) / 4;
        cvt_tf32_kernel<<<(n4 + 255) / 256, 256>>>(hs, (float*)pht, n4);
        n4 = (HID * HID) / 4;
        cvt_tf32_kernel<<<(n4 + 255) / 256, 256>>>(q_w, (float*)pqt, n4);
        cvt_tf32_kernel<<<(n4 + 255) / 256, 256>>>(o_w, (float*)pot, n4);
        n4 = (KVW * HID) / 4;
        cvt_tf32_kernel<<<(n4 + 255) / 256, 256>>>(k_w, (float*)pkt, n4);
        cvt_tf32_kernel<<<(n4 + 255) / 256, 256>>>(v_w, (float*)pvt, n4);
    }

    // 1. RoPE table
    rope_table_kernel<<<(S_LEN * 64 + 255) / 256, 256>>>();

    // 2. fused Q/K/V projections (tensor pipe, pipelined, cvt-free)
    qkv_kernel<<<dim3(24, S_LEN / 128), 256, GEMM_SMEM>>>(q_b, k_b, v_b);

    // 3. RoPE on q and k
    rope_apply_kernel<<<(S_LEN * NH * 64 + 255) / 256, 256>>>(qf, NH, S_LEN * NH * 64);
    rope_apply_kernel<<<(S_LEN * NKV * 64 + 255) / 256, 256>>>(kf, NKV, S_LEN * NKV * 64);

    // 4. causal flash attention (GQA), tensor pipe
    flash_tf32_kernel<<<dim3(32, NH), 256, FL_SMEM>>>(qf, kf, vf, af);

    // 5. output projection (cvt-free)
    oproj_kernel<<<dim3(HID / 128, S_LEN / 128), 256, GEMM_SMEM>>>(out);
}